// round 16
// baseline (speedup 1.0000x reference)
#include <cuda_runtime.h>
#include <stdint.h>

#define EN    1024
#define ED    64
#define SP    32768
#define NPOS  131072
#define MARGIN 6e-4f

// screen smem (bytes): eq 2x8KB | cn 2x1KB
#define EQB(i) ((i) * 8192)
#define CNB(i) (16384 + (i) * 1024)
#define SMEM_BYTES 18432

__device__ float    g_norms[EN];
__device__ int      g_eq[EN * 16];     // packed int8 codebook, 16 words/code
__device__ float2   g_cn[EN];          // (-2*r_e, ||e||^2) per code
__device__ uint2    g_top[NPOS];
__device__ unsigned g_flagcnt;
__device__ unsigned g_flaglist[NPOS];

__device__ __forceinline__ unsigned sptr(const void* p) {
    return (unsigned)__cvta_generic_to_shared(p);
}
#define CP16(d, s)  asm volatile("cp.async.cg.shared.global [%0], [%1], 16;" :: "r"(d), "l"(s) : "memory")
#define CP_COMMIT() asm volatile("cp.async.commit_group;" ::: "memory")
#define CP_WAIT0()  asm volatile("cp.async.wait_group 0;" ::: "memory")

// ---------------- K1: prep = norms (proven order) + int8-quantized codebook ----------------
__global__ __launch_bounds__(256) void vq_prep_kernel(const float* __restrict__ emb) {
    int j = blockIdx.x * 256 + threadIdx.x;
    if (j == 0) g_flagcnt = 0;
    if (j >= EN) return;
    const float4* row = (const float4*)(emb + j * ED);
    float s = 0.f, m = 0.f;
#pragma unroll
    for (int k = 0; k < ED / 4; k++) {
        float4 v = row[k];
        s += v.x * v.x + v.y * v.y + v.z * v.z + v.w * v.w;
        m = fmaxf(m, fmaxf(fmaxf(fabsf(v.x), fabsf(v.y)), fmaxf(fabsf(v.z), fabsf(v.w))));
    }
    g_norms[j] = s;
    float sc = (m > 0.f) ? 127.0f / m : 0.f;
    float re = (m > 0.f) ? m / 127.0f : 0.f;
    const float* e = emb + j * ED;
#pragma unroll
    for (int w = 0; w < 16; w++) {
        int p = 0;
#pragma unroll
        for (int b = 0; b < 4; b++) {
            int q = __float2int_rn(e[4 * w + b] * sc);
            p |= (q & 0xFF) << (8 * b);
        }
        g_eq[j * 16 + w] = p;
    }
    g_cn[j] = make_float2(-2.0f * re, s);
}

// ---------------- K2: DP4A screen (2 positions/thread) ----------------
__global__ __launch_bounds__(128, 3)
void vq_screen_kernel(const float* __restrict__ z) {
    extern __shared__ char smraw[];
    const unsigned sb = sptr(smraw);
    const int tid = threadIdx.x;

    const int p0 = blockIdx.x * 256 + tid;
    const int p1 = p0 + 128;
    const int b  = p0 >> 15;
    const int base0 = b * (ED * SP) + (p0 & (SP - 1));
    const int base1 = b * (ED * SP) + (p1 & (SP - 1));

    // prefetch chunk 0: 128 codes x 64B + 128 float2 scale/norm
    {
        const char* src = (const char*)g_eq;
#pragma unroll
        for (int i = 0; i < 4; i++)
            CP16(sb + EQB(0) + (tid + i * 128) * 16, src + (tid + i * 128) * 16);
        if (tid < 64)
            CP16(sb + CNB(0) + tid * 16, (const char*)g_cn + tid * 16);
        CP_COMMIT();
    }

    // pass 1: per-position max|x|
    float m0 = 0.f, m1 = 0.f;
#pragma unroll
    for (int k = 0; k < ED; k++) {
        m0 = fmaxf(m0, fabsf(z[base0 + k * SP]));
        m1 = fmaxf(m1, fabsf(z[base1 + k * SP]));
    }
    const float s0 = 127.0f / m0, s1 = 127.0f / m1;
    const float rx0 = m0 / 127.0f, rx1 = m1 / 127.0f;

    // pass 2: quantize + pack x into 16 int32 per position
    int xq0[16], xq1[16];
#pragma unroll
    for (int w = 0; w < 16; w++) {
        int pa = 0, pb = 0;
#pragma unroll
        for (int bb = 0; bb < 4; bb++) {
            int qa = __float2int_rn(z[base0 + (4 * w + bb) * SP] * s0);
            int qb = __float2int_rn(z[base1 + (4 * w + bb) * SP] * s1);
            pa |= (qa & 0xFF) << (8 * bb);
            pb |= (qb & 0xFF) << (8 * bb);
        }
        xq0[w] = pa; xq1[w] = pb;
    }

    float v1a = 3.4e38f, v2a = 3.4e38f, v3a = 3.4e38f;
    float v1b = 3.4e38f, v2b = 3.4e38f, v3b = 3.4e38f;
    int i1a = 0, i2a = 0, i1b = 0, i2b = 0;

    CP_WAIT0();
    __syncthreads();

#pragma unroll 1
    for (int c = 0; c < 8; c++) {
        if (c < 7) {
            const char* src = (const char*)(g_eq + (c + 1) * 128 * 16);
#pragma unroll
            for (int i = 0; i < 4; i++)
                CP16(sb + EQB((c + 1) & 1) + (tid + i * 128) * 16, src + (tid + i * 128) * 16);
            if (tid < 64)
                CP16(sb + CNB((c + 1) & 1) + tid * 16,
                     (const char*)(g_cn + (c + 1) * 128) + tid * 16);
            CP_COMMIT();
        }
        const int*    eq = (const int*)   (smraw + EQB(c & 1));
        const float2* cn = (const float2*)(smraw + CNB(c & 1));
        const int cbase = c * 128;

#pragma unroll 2
        for (int j = 0; j < 128; j += 2) {
            const int* e0 = eq + j * 16;
            const int* e1 = e0 + 16;
            int a00 = 0, a01 = 0, a10 = 0, a11 = 0;   // [pos][code]
#pragma unroll
            for (int w = 0; w < 16; w++) {
                int ew0 = e0[w], ew1 = e1[w];          // LDS broadcast
                a00 = __dp4a(xq0[w], ew0, a00);
                a01 = __dp4a(xq0[w], ew1, a01);
                a10 = __dp4a(xq1[w], ew0, a10);
                a11 = __dp4a(xq1[w], ew1, a11);
            }
            float2 c0 = cn[j], c1 = cn[j + 1];
            float t00 = c0.x * rx0, t01 = c1.x * rx0;
            float t10 = c0.x * rx1, t11 = c1.x * rx1;
            float d00 = fmaf((float)a00, t00, c0.y);
            float d01 = fmaf((float)a01, t01, c1.y);
            float d10 = fmaf((float)a10, t10, c0.y);
            float d11 = fmaf((float)a11, t11, c1.y);
            int col0 = cbase + j, col1 = cbase + j + 1;
            if (d00 < v1a)      { v3a = v2a; v2a = v1a; i2a = i1a; v1a = d00; i1a = col0; }
            else if (d00 < v2a) { v3a = v2a; v2a = d00; i2a = col0; }
            else if (d00 < v3a) { v3a = d00; }
            if (d01 < v1a)      { v3a = v2a; v2a = v1a; i2a = i1a; v1a = d01; i1a = col1; }
            else if (d01 < v2a) { v3a = v2a; v2a = d01; i2a = col1; }
            else if (d01 < v3a) { v3a = d01; }
            if (d10 < v1b)      { v3b = v2b; v2b = v1b; i2b = i1b; v1b = d10; i1b = col0; }
            else if (d10 < v2b) { v3b = v2b; v2b = d10; i2b = col0; }
            else if (d10 < v3b) { v3b = d10; }
            if (d11 < v1b)      { v3b = v2b; v2b = v1b; i2b = i1b; v1b = d11; i1b = col1; }
            else if (d11 < v2b) { v3b = v2b; v2b = d11; i2b = col1; }
            else if (d11 < v3b) { v3b = d11; }
        }
        if (c < 7) CP_WAIT0();
        __syncthreads();
    }

    unsigned f2a = (__fsub_rn(v2a, v1a) <= MARGIN) ? 0x80000000u : 0u;
    unsigned f2b = (__fsub_rn(v2b, v1b) <= MARGIN) ? 0x80000000u : 0u;
    g_top[p0] = make_uint2((unsigned)i1a | f2a, (unsigned)i2a);
    g_top[p1] = make_uint2((unsigned)i1b | f2b, (unsigned)i2b);
    if (__fsub_rn(v3a, v1a) <= MARGIN) g_flaglist[atomicAdd(&g_flagcnt, 1u)] = p0;
    if (__fsub_rn(v3b, v1b) <= MARGIN) g_flaglist[atomicAdd(&g_flagcnt, 1u)] = p1;
}

// ---------------- K3: finalize (exact reference-rounded top-2 rescore + scatter) ----------------
__global__ __launch_bounds__(256) void vq_finalize_kernel(const float* __restrict__ z,
                                                          const float* __restrict__ emb,
                                                          float* __restrict__ out) {
    int pos = blockIdx.x * 256 + threadIdx.x;
    uint2 t = g_top[pos];
    int i1 = (int)(t.x & 0x7FFFFFFFu), i2 = (int)t.y;
    int base = (pos >> 15) * (ED * SP) + (pos & (SP - 1));
    int idx = i1;
    if (t.x & 0x80000000u) {
        float xn = 0.f, d1 = 0.f, d2 = 0.f;
        const float* e1 = emb + i1 * ED;
        const float* e2 = emb + i2 * ED;
#pragma unroll
        for (int k = 0; k < ED; k++) {
            float x = z[base + k * SP];
            xn = __fadd_rn(xn, __fmul_rn(x, x));
            d1 = fmaf(x, e1[k], d1);
            d2 = fmaf(x, e2[k], d2);
        }
        float dd1 = __fsub_rn(__fadd_rn(xn, g_norms[i1]), __fmul_rn(2.0f, d1));
        float dd2 = __fsub_rn(__fadd_rn(xn, g_norms[i2]), __fmul_rn(2.0f, d2));
        if (dd2 < dd1 || (dd2 == dd1 && i2 < i1)) idx = i2;
    }
    const float4* er = (const float4*)(emb + idx * ED);
#pragma unroll
    for (int k = 0; k < ED / 4; k++) {
        float4 v = er[k];
        out[base + (4 * k + 0) * SP] = v.x;
        out[base + (4 * k + 1) * SP] = v.y;
        out[base + (4 * k + 2) * SP] = v.z;
        out[base + (4 * k + 3) * SP] = v.w;
    }
}

// ---------------- K4: coalesced full exact scan (warp/position, lanes own dims) ----------------
__global__ __launch_bounds__(128) void vq_fullscan_kernel(const float* __restrict__ z,
                                                          const float* __restrict__ emb,
                                                          float* __restrict__ out) {
    int w = (blockIdx.x * 128 + threadIdx.x) >> 5, lid = threadIdx.x & 31;
    int nw = gridDim.x * 4;
    unsigned cnt = g_flagcnt;
    for (unsigned f = w; f < cnt; f += nw) {
        int pos = g_flaglist[f];
        int base = (pos >> 15) * (ED * SP) + (pos & (SP - 1));
        // lane owns dims 2*lid, 2*lid+1
        float xa = z[base + (2 * lid) * SP];
        float xb = z[base + (2 * lid + 1) * SP];
        float xn = __fadd_rn(__fmul_rn(xa, xa), __fmul_rn(xb, xb));
#pragma unroll
        for (int o = 16; o; o >>= 1)
            xn = __fadd_rn(xn, __shfl_xor_sync(0xFFFFFFFFu, xn, o));

        float best = 3.4e38f; int bi = 0;
#pragma unroll 2
        for (int j = 0; j < EN; j++) {
            float2 e2 = *(const float2*)(emb + j * ED + 2 * lid);   // coalesced
            float p = fmaf(xb, e2.y, __fmul_rn(xa, e2.x));
#pragma unroll
            for (int o = 16; o; o >>= 1)
                p = __fadd_rn(p, __shfl_xor_sync(0xFFFFFFFFu, p, o));
            float d = __fsub_rn(__fadd_rn(xn, g_norms[j]), __fmul_rn(2.0f, p));
            if (d < best) { best = d; bi = j; }   // ascending j: strict < keeps lowest
        }
        out[base + (2 * lid) * SP]     = emb[bi * ED + 2 * lid];
        out[base + (2 * lid + 1) * SP] = emb[bi * ED + 2 * lid + 1];
    }
}

// ---------------- launcher ----------------
extern "C" void kernel_launch(void* const* d_in, const int* in_sizes, int n_in,
                              void* d_out, int out_size) {
    const float* z   = (const float*)d_in[0];
    const float* emb = (const float*)d_in[1];
    if (n_in >= 2 && in_sizes[0] == EN * ED && in_sizes[1] != EN * ED) {
        z = (const float*)d_in[1]; emb = (const float*)d_in[0];
    }
    float* out = (float*)d_out;

    cudaFuncSetAttribute(vq_screen_kernel,
                         cudaFuncAttributeMaxDynamicSharedMemorySize, SMEM_BYTES);
    vq_prep_kernel<<<4, 256>>>(emb);
    vq_screen_kernel<<<NPOS / 256, 128, SMEM_BYTES>>>(z);
    vq_finalize_kernel<<<NPOS / 256, 256>>>(z, emb, out);
    vq_fullscan_kernel<<<128, 128>>>(z, emb, out);
}

// round 17
// speedup vs baseline: 9.0186x; 9.0186x over previous
#include <cuda_runtime.h>
#include <stdint.h>

#define EN    1024
#define ED    64
#define SP    32768
#define NPOS  131072

// smem map (bytes)
#define EB(i)   ((i) * 16384)        // 2 x 64-code fp32 chunk
#define SN(i)   (32768 + (i) * 256)  // 2 x 64 norms
#define SLAB    33280                // 2 buf x 2 pair x 2 half x 32 lane x 16B = 4KB
#define XNS     37376                // 2 pair x 2 half x 32 lane x 8B = 2KB
#define MG      39424                // 2 pair x 32 lane x 16B = 1KB
#define SMEM_BYTES 40448

__device__ float g_norms[EN];

__device__ __forceinline__ unsigned sptr(const void* p) {
    return (unsigned)__cvta_generic_to_shared(p);
}
#define CP16(d, s)  asm volatile("cp.async.cg.shared.global [%0], [%1], 16;" :: "r"(d), "l"(s) : "memory")
#define CP_COMMIT() asm volatile("cp.async.commit_group;" ::: "memory")
#define CP_WAIT0()  asm volatile("cp.async.wait_group 0;" ::: "memory")
#define FM(a, x, e) asm("fma.rn.f32x2 %0, %1, %2, %0;" : "+l"(a) : "l"(x), "l"(e))
#define PAIR_BAR(p) asm volatile("bar.sync %0, 64;" :: "r"(1 + (p)) : "memory")

// ---------------- K1: norms ----------------
__global__ void vq_norms_kernel(const float* __restrict__ emb) {
    int j = blockIdx.x * blockDim.x + threadIdx.x;
    if (j < EN) {
        const float4* row = (const float4*)(emb + j * ED);
        float s = 0.f;
#pragma unroll
        for (int k = 0; k < ED / 4; k++) {
            float4 v = row[k];
            s += v.x * v.x + v.y * v.y + v.z * v.z + v.w * v.w;
        }
        g_norms[j] = s;
    }
}

// ---------------- K2: dims-split argmin (4 warps/SMSP) ----------------
// warp w: pair p = w&1 (position group), half h = w>>1 (dim group).
// thread (p,h,lane) owns positions P0 = cta*128 + p*64 + lane, P1 = P0+32,
// and dims [h*32, h*32+32). Partner warp (other h) supplies the complement
// of each dot via a smem slab + 64-thread named barrier per 4-code block.
__global__ __launch_bounds__(128, 4)
void vq_argmin_kernel(const float* __restrict__ z,
                      const float* __restrict__ emb,
                      float* __restrict__ out) {
    extern __shared__ char sm[];
    const unsigned sb = sptr(sm);
    const int tid = threadIdx.x;
    const int w = tid >> 5, lane = tid & 31;
    const int p = w & 1, h = w >> 1;

    const int P0 = blockIdx.x * 128 + p * 64 + lane;
    const int P1 = P0 + 32;
    const int b  = P0 >> 15;                    // both pos same batch (128 | 32768)
    const int base0 = b * (ED * SP) + (P0 & (SP - 1));
    const int base1 = b * (ED * SP) + (P1 & (SP - 1));

    // prefetch chunk 0 + norms
    {
        const char* src = (const char*)emb;
#pragma unroll
        for (int i = 0; i < 8; i++)
            CP16(sb + EB(0) + (tid + i * 128) * 16, src + (tid + i * 128) * 16);
        if (tid < 16)
            CP16(sb + SN(0) + tid * 16, (const char*)g_norms + tid * 16);
        CP_COMMIT();
    }

    // x halves -> packed f32x2 regs + partial xn (R3-pattern order per half)
    unsigned long long xA[16], xB[16];
    float xnp0 = 0.f, xnp1 = 0.f;
#pragma unroll
    for (int k = 0; k < 32; k += 2) {
        int kk = h * 32 + k;
        float a = z[base0 + kk * SP];
        float c = z[base0 + (kk + 1) * SP];
        xnp0 = __fadd_rn(xnp0, __fmul_rn(a, a));
        xnp0 = __fadd_rn(xnp0, __fmul_rn(c, c));
        asm("mov.b64 %0, {%1, %2};" : "=l"(xA[k >> 1]) : "f"(a), "f"(c));
        float d = z[base1 + kk * SP];
        float e = z[base1 + (kk + 1) * SP];
        xnp1 = __fadd_rn(xnp1, __fmul_rn(d, d));
        xnp1 = __fadd_rn(xnp1, __fmul_rn(e, e));
        asm("mov.b64 %0, {%1, %2};" : "=l"(xB[k >> 1]) : "f"(d), "f"(e));
    }

    // exchange xn halves (once): xn = lo_half + hi_half (both threads identical)
    float* xns = (float*)(sm + XNS);
    xns[((p * 2 + h) * 32 + lane) * 2 + 0] = xnp0;
    xns[((p * 2 + h) * 32 + lane) * 2 + 1] = xnp1;
    CP_WAIT0();
    __syncthreads();
    const float xn0 = __fadd_rn(xns[((p * 2 + 0) * 32 + lane) * 2 + 0],
                                xns[((p * 2 + 1) * 32 + lane) * 2 + 0]);
    const float xn1 = __fadd_rn(xns[((p * 2 + 0) * 32 + lane) * 2 + 1],
                                xns[((p * 2 + 1) * 32 + lane) * 2 + 1]);

    float best0 = 3.4e38f, best1 = 3.4e38f;
    int   bi0 = 0, bi1 = 0;

#pragma unroll 1
    for (int c = 0; c < 16; c++) {               // 16 chunks x 64 codes
        if (c < 15) {
            const char* src = (const char*)(emb + (c + 1) * 64 * ED);
#pragma unroll
            for (int i = 0; i < 8; i++)
                CP16(sb + EB((c + 1) & 1) + (tid + i * 128) * 16, src + (tid + i * 128) * 16);
            if (tid < 16)
                CP16(sb + SN((c + 1) & 1) + tid * 16,
                     (const char*)(g_norms + (c + 1) * 64) + tid * 16);
            CP_COMMIT();
        }
        const char*  ebuf = sm + EB(c & 1);
        const float* snrm = (const float*)(sm + SN(c & 1));

#pragma unroll 1
        for (int jb = 0; jb < 16; jb++) {        // 4 codes per block
            const char* eb = ebuf + jb * 4 * 256 + h * 128;
            unsigned long long ac[4][2] = {};    // [code][pos], single chain each
#pragma unroll
            for (int q = 0; q < 8; q++) {
#pragma unroll
                for (int cc = 0; cc < 4; cc++) {
                    ulonglong2 v = *(const ulonglong2*)(eb + cc * 256 + q * 16);
                    FM(ac[cc][0], xA[2 * q], v.x);
                    FM(ac[cc][0], xA[2 * q + 1], v.y);
                    FM(ac[cc][1], xB[2 * q], v.x);
                    FM(ac[cc][1], xB[2 * q + 1], v.y);
                }
            }
            // partials: lo+hi of each packed chain
            float part[4][2];
#pragma unroll
            for (int cc = 0; cc < 4; cc++)
#pragma unroll
                for (int pp = 0; pp < 2; pp++) {
                    float lo, hi;
                    asm("mov.b64 {%0,%1}, %2;" : "=f"(lo), "=f"(hi) : "l"(ac[cc][pp]));
                    part[cc][pp] = lo + hi;
                }
            // store the 2 codes the PARTNER epilogues; h=0 keeps {0,1}, h=1 keeps {2,3}
            const int buf = jb & 1;
            float* slab = (float*)(sm + SLAB);
            float* st = slab + (((buf * 2 + p) * 2 + h) * 32 + lane) * 4;
            int sc = (h == 0) ? 2 : 0;           // codes I store = codes partner epilogues
            st[0] = part[sc][0];   st[1] = part[sc][1];
            st[2] = part[sc + 1][0]; st[3] = part[sc + 1][1];
            PAIR_BAR(p);
            const float* ld = slab + (((buf * 2 + p) * 2 + (1 - h)) * 32 + lane) * 4;
            int ec = (h == 0) ? 0 : 2;           // codes I epilogue
            int gc = c * 64 + jb * 4 + ec;
            float en0c = snrm[jb * 4 + ec], en1c = snrm[jb * 4 + ec + 1];
            {
                float dot = __fadd_rn(part[ec][0], ld[0]);
                float d = __fsub_rn(__fadd_rn(xn0, en0c), __fmul_rn(2.0f, dot));
                if (d < best0) { best0 = d; bi0 = gc; }
                dot = __fadd_rn(part[ec][1], ld[1]);
                d = __fsub_rn(__fadd_rn(xn1, en0c), __fmul_rn(2.0f, dot));
                if (d < best1) { best1 = d; bi1 = gc; }
                dot = __fadd_rn(part[ec + 1][0], ld[2]);
                d = __fsub_rn(__fadd_rn(xn0, en1c), __fmul_rn(2.0f, dot));
                if (d < best0) { best0 = d; bi0 = gc + 1; }
                dot = __fadd_rn(part[ec + 1][1], ld[3]);
                d = __fsub_rn(__fadd_rn(xn1, en1c), __fmul_rn(2.0f, dot));
                if (d < best1) { best1 = d; bi1 = gc + 1; }
            }
        }
        if (c < 15) CP_WAIT0();
        __syncthreads();
    }

    // merge halves: h=1 publishes, h=0 combines (lowest-index on exact ties)
    if (h == 1) {
        float4* mg = (float4*)(sm + MG);
        float4 v;
        v.x = best0; v.y = __int_as_float(bi0);
        v.z = best1; v.w = __int_as_float(bi1);
        mg[p * 32 + lane] = v;
    }
    __syncthreads();
    if (h == 0) {
        float4 v = ((const float4*)(sm + MG))[p * 32 + lane];
        float hb0 = v.x, hb1 = v.z;
        int hi0 = __float_as_int(v.y), hi1 = __float_as_int(v.w);
        if (hb0 < best0 || (hb0 == best0 && hi0 < bi0)) { best0 = hb0; bi0 = hi0; }
        if (hb1 < best1 || (hb1 == best1 && hi1 < bi1)) { best1 = hb1; bi1 = hi1; }

        const float4* er0 = (const float4*)(emb + bi0 * ED);
        const float4* er1 = (const float4*)(emb + bi1 * ED);
#pragma unroll
        for (int k = 0; k < ED / 4; k++) {
            float4 a = er0[k];
            out[base0 + (4 * k + 0) * SP] = a.x;
            out[base0 + (4 * k + 1) * SP] = a.y;
            out[base0 + (4 * k + 2) * SP] = a.z;
            out[base0 + (4 * k + 3) * SP] = a.w;
            float4 w4 = er1[k];
            out[base1 + (4 * k + 0) * SP] = w4.x;
            out[base1 + (4 * k + 1) * SP] = w4.y;
            out[base1 + (4 * k + 2) * SP] = w4.z;
            out[base1 + (4 * k + 3) * SP] = w4.w;
        }
    }
}

// ---------------- launcher ----------------
extern "C" void kernel_launch(void* const* d_in, const int* in_sizes, int n_in,
                              void* d_out, int out_size) {
    const float* z   = (const float*)d_in[0];
    const float* emb = (const float*)d_in[1];
    if (n_in >= 2 && in_sizes[0] == EN * ED && in_sizes[1] != EN * ED) {
        z = (const float*)d_in[1]; emb = (const float*)d_in[0];
    }
    float* out = (float*)d_out;

    cudaFuncSetAttribute(vq_argmin_kernel,
                         cudaFuncAttributeMaxDynamicSharedMemorySize, SMEM_BYTES);
    vq_norms_kernel<<<(EN + 255) / 256, 256>>>(emb);
    vq_argmin_kernel<<<NPOS / 128, 128, SMEM_BYTES>>>(z, emb, out);
}